// round 1
// baseline (speedup 1.0000x reference)
#include <cuda_runtime.h>
#include <cuda_bf16.h>

// Shapes (compile-time constants)
#define NB   512           // sequence length
#define DD   256           // model dim
#define HH   8             // heads
#define HDD  32            // head dim
#define HID  682           // swiglu hidden
#define QKVD 768

// ---------------- device scratch ----------------
__device__ float g_xn[NB * DD];
__device__ float g_qkv[NB * QKVD];
__device__ float g_Pb[NB * DD];
__device__ float g_Pv[NB * DD];
__device__ float g_y[NB * DD];
__device__ float g_xn2[NB * DD];
__device__ float g_h1a[NB * HID];
__device__ float g_h1b[NB * HID];
__device__ float g_h1[NB * HID];

__device__ __forceinline__ float silu_f(float v) {
    return v / (1.0f + __expf(-v));
}

// ---------------- LayerNorm: one block per row, 256 threads ----------------
__global__ __launch_bounds__(256) void ln_kernel(const float* __restrict__ x,
                                                 const float* __restrict__ w,
                                                 const float* __restrict__ b,
                                                 float* __restrict__ out) {
    int row = blockIdx.x, t = threadIdx.x;
    float v = x[row * DD + t];
    float s = v, q = v * v;
#pragma unroll
    for (int o = 16; o; o >>= 1) {
        s += __shfl_xor_sync(0xffffffff, s, o);
        q += __shfl_xor_sync(0xffffffff, q, o);
    }
    __shared__ float ss[8], sq[8];
    int warp = t >> 5, lane = t & 31;
    if (lane == 0) { ss[warp] = s; sq[warp] = q; }
    __syncthreads();
    s = 0.f; q = 0.f;
#pragma unroll
    for (int k = 0; k < 8; k++) { s += ss[k]; q += sq[k]; }
    float mean = s * (1.0f / DD);
    float var = q * (1.0f / DD) - mean * mean;
    out[row * DD + t] = (v - mean) * rsqrtf(var + 1e-5f) * w[t] + b[t];
}

// ---------------- coords projection: Pb = coords @ rb1^T, Pv = coords @ rv1^T -------
__global__ __launch_bounds__(256) void proj3_kernel(const float* __restrict__ coords,
                                                    const float* __restrict__ rb1,
                                                    const float* __restrict__ rv1,
                                                    float* __restrict__ Pb,
                                                    float* __restrict__ Pv) {
    int i = blockIdx.x, k = threadIdx.x;
    float c0 = coords[i * 3 + 0], c1 = coords[i * 3 + 1], c2 = coords[i * 3 + 2];
    Pb[i * DD + k] = rb1[k * 3 + 0] * c0 + rb1[k * 3 + 1] * c1 + rb1[k * 3 + 2] * c2;
    Pv[i * DD + k] = rv1[k * 3 + 0] * c0 + rv1[k * 3 + 1] * c1 + rv1[k * 3 + 2] * c2;
}

// ---------------- generic C = A @ W^T (+bias) (+residual) ----------------
// A:[M,K] row-major, W:[N,K] row-major, C:[M,N]
__global__ __launch_bounds__(256) void gemm_xwt(const float* __restrict__ A,
                                                const float* __restrict__ W,
                                                const float* __restrict__ bias,
                                                const float* __restrict__ residual,
                                                float* __restrict__ C,
                                                int M, int N, int K) {
    __shared__ float As[32][33];
    __shared__ float Ws[32][33];
    int tx = threadIdx.x;   // 0..31 -> n within tile / k for loading
    int ty = threadIdx.y;   // 0..7
    int row0 = blockIdx.y * 32, col0 = blockIdx.x * 32;
    float acc[4] = {0.f, 0.f, 0.f, 0.f};
    for (int k0 = 0; k0 < K; k0 += 32) {
#pragma unroll
        for (int r = 0; r < 4; r++) {
            int m = ty * 4 + r;
            int ak = k0 + tx;
            int arow = row0 + m;
            As[m][tx] = (arow < M && ak < K) ? A[arow * K + ak] : 0.f;
            int wrow = col0 + m;
            Ws[m][tx] = (wrow < N && ak < K) ? W[wrow * K + ak] : 0.f;
        }
        __syncthreads();
#pragma unroll
        for (int kk = 0; kk < 32; kk++) {
            float wv = Ws[tx][kk];
#pragma unroll
            for (int r = 0; r < 4; r++)
                acc[r] += As[ty * 4 + r][kk] * wv;
        }
        __syncthreads();
    }
#pragma unroll
    for (int r = 0; r < 4; r++) {
        int m = row0 + ty * 4 + r, n = col0 + tx;
        if (m < M && n < N) {
            float v = acc[r];
            if (bias) v += bias[n];
            if (residual) v += residual[m * N + n];
            C[m * N + n] = v;
        }
    }
}

// ---------------- fused attention: one block per query i ----------------
// logits[h][j] = q_h(i).k_h(j)/sqrt(32) + rb2[h,:].silu(Pb[i]+bb1 - Pb[j]) + bb2[h]
// w = softmax_j
// T[h,k]   = sum_j w[h,j] * silu(Pv[i,k]+bv1[k] - Pv[j,k])
// out[i,d] = x[i,d] + sum_j w[h,j]*V[j,d] + rv2[d,:].T[h,:] + bv2[d],  h = d>>5
__global__ __launch_bounds__(256) void attn_kernel(
    const float* __restrict__ x, const float* __restrict__ qkv,
    const float* __restrict__ Pb, const float* __restrict__ Pv,
    const float* __restrict__ rb1_b, const float* __restrict__ rb2_w,
    const float* __restrict__ rb2_b, const float* __restrict__ rv1_b,
    const float* __restrict__ rv2_w, const float* __restrict__ rv2_b,
    float* __restrict__ y) {
    const int i = blockIdx.x;
    const int t = threadIdx.x;

    __shared__ __align__(16) float sm_q[DD];
    __shared__ __align__(16) float sm_pbq[DD];
    __shared__ __align__(16) float sm_rb2[HH * DD];
    __shared__ __align__(16) float sm_w[NB * HH];   // logits -> softmax weights, [j][h]
    __shared__ __align__(16) float sm_T[HH * DD];

    sm_q[t] = qkv[i * QKVD + t];
    sm_pbq[t] = Pb[i * DD + t] + rb1_b[t];
#pragma unroll
    for (int h = 0; h < HH; h++) sm_rb2[h * DD + t] = rb2_w[h * DD + t];
    __syncthreads();

    const float4* q4 = (const float4*)sm_q;
    const float4* pq4 = (const float4*)sm_pbq;
    const float4* rb24 = (const float4*)sm_rb2;

    float bb2[HH];
#pragma unroll
    for (int h = 0; h < HH; h++) bb2[h] = rb2_b[h];

    // ---- Phase A: logits for j = t and j = t+256 ----
#pragma unroll 1
    for (int jj = 0; jj < 2; jj++) {
        int j = t + jj * 256;
        const float4* Kj = (const float4*)(qkv + j * QKVD + DD);
        const float4* Pbj = (const float4*)(Pb + j * DD);
        float ba[HH] = {0.f, 0.f, 0.f, 0.f, 0.f, 0.f, 0.f, 0.f};
        float qa[HH];
#pragma unroll
        for (int h = 0; h < HH; h++) {
            float q_acc = 0.f;
#pragma unroll
            for (int c = 0; c < 8; c++) {
                int kc = h * 8 + c;
                float4 kv = Kj[kc], pb = Pbj[kc];
                float4 qv = q4[kc], pq = pq4[kc];
                q_acc += qv.x * kv.x + qv.y * kv.y + qv.z * kv.z + qv.w * kv.w;
                float4 u;
                u.x = silu_f(pq.x - pb.x);
                u.y = silu_f(pq.y - pb.y);
                u.z = silu_f(pq.z - pb.z);
                u.w = silu_f(pq.w - pb.w);
#pragma unroll
                for (int hh = 0; hh < HH; hh++) {
                    float4 rv = rb24[hh * 64 + kc];
                    ba[hh] += rv.x * u.x + rv.y * u.y + rv.z * u.z + rv.w * u.w;
                }
            }
            qa[h] = q_acc;
        }
#pragma unroll
        for (int h = 0; h < HH; h++)
            sm_w[j * HH + h] = qa[h] * 0.17677669529663687f + ba[h] + bb2[h];
    }
    __syncthreads();

    // ---- softmax: warp w handles head w ----
    {
        int warp = t >> 5, lane = t & 31;
        int h = warp;  // 8 warps, 8 heads
        float m = -1e30f;
        for (int j = lane; j < NB; j += 32) m = fmaxf(m, sm_w[j * HH + h]);
#pragma unroll
        for (int o = 16; o; o >>= 1) m = fmaxf(m, __shfl_xor_sync(0xffffffff, m, o));
        float s = 0.f;
        for (int j = lane; j < NB; j += 32) {
            float e = __expf(sm_w[j * HH + h] - m);
            sm_w[j * HH + h] = e;
            s += e;
        }
#pragma unroll
        for (int o = 16; o; o >>= 1) s += __shfl_xor_sync(0xffffffff, s, o);
        float inv = 1.0f / s;
        for (int j = lane; j < NB; j += 32) sm_w[j * HH + h] *= inv;
    }
    __syncthreads();

    // ---- Phase B: T[h,k] accumulation, thread t owns k = t ----
    {
        float pvq = Pv[i * DD + t] + rv1_b[t];
        float T[HH] = {0.f, 0.f, 0.f, 0.f, 0.f, 0.f, 0.f, 0.f};
        const float4* w4 = (const float4*)sm_w;
#pragma unroll 4
        for (int j = 0; j < NB; j++) {
            float sv = silu_f(pvq - Pv[j * DD + t]);
            float4 w0 = w4[j * 2], w1 = w4[j * 2 + 1];
            T[0] += w0.x * sv; T[1] += w0.y * sv; T[2] += w0.z * sv; T[3] += w0.w * sv;
            T[4] += w1.x * sv; T[5] += w1.y * sv; T[6] += w1.z * sv; T[7] += w1.w * sv;
        }
#pragma unroll
        for (int h = 0; h < HH; h++) sm_T[h * DD + t] = T[h];
    }
    __syncthreads();

    // ---- output: context1 + context2 + residual ----
    {
        int d = t;
        int h = d >> 5;
        float c1 = 0.f;
#pragma unroll 4
        for (int j = 0; j < NB; j++)
            c1 += sm_w[j * HH + h] * qkv[j * QKVD + 2 * DD + d];
        float c2 = rv2_b[d];
        const float4* rv2r = (const float4*)(rv2_w + d * DD);
        const float4* Ts = (const float4*)(sm_T + h * DD);
#pragma unroll 8
        for (int c = 0; c < 64; c++) {
            float4 rv = rv2r[c], tv = Ts[c];
            c2 += rv.x * tv.x + rv.y * tv.y + rv.z * tv.z + rv.w * tv.w;
        }
        y[i * DD + d] = x[i * DD + d] + c1 + c2;
    }
}

// ---------------- SwiGLU combine: h1 = silu(a) * g ----------------
__global__ void ffn_combine(const float* __restrict__ a, const float* __restrict__ g,
                            float* __restrict__ o, int n) {
    int idx = blockIdx.x * blockDim.x + threadIdx.x;
    if (idx < n) {
        float v = a[idx];
        o[idx] = (v / (1.0f + __expf(-v))) * g[idx];
    }
}

// ---------------- host launcher ----------------
extern "C" void kernel_launch(void* const* d_in, const int* in_sizes, int n_in,
                              void* d_out, int out_size) {
    const float* x      = (const float*)d_in[0];
    const float* coords = (const float*)d_in[1];
    const float* ln1_w  = (const float*)d_in[2];
    const float* ln1_b  = (const float*)d_in[3];
    const float* ln2_w  = (const float*)d_in[4];
    const float* ln2_b  = (const float*)d_in[5];
    const float* qkv_w  = (const float*)d_in[6];
    const float* qkv_b  = (const float*)d_in[7];
    const float* rb1_w  = (const float*)d_in[8];
    const float* rb1_b  = (const float*)d_in[9];
    const float* rb2_w  = (const float*)d_in[10];
    const float* rb2_b  = (const float*)d_in[11];
    const float* rv1_w  = (const float*)d_in[12];
    const float* rv1_b  = (const float*)d_in[13];
    const float* rv2_w  = (const float*)d_in[14];
    const float* rv2_b  = (const float*)d_in[15];
    const float* ffn_w1 = (const float*)d_in[16];
    const float* ffn_b1 = (const float*)d_in[17];
    const float* ffn_w2 = (const float*)d_in[18];
    const float* ffn_b2 = (const float*)d_in[19];
    const float* ffn_w3 = (const float*)d_in[20];
    const float* ffn_b3 = (const float*)d_in[21];
    float* out = (float*)d_out;

    float *p_xn, *p_qkv, *p_Pb, *p_Pv, *p_y, *p_xn2, *p_h1a, *p_h1b, *p_h1;
    cudaGetSymbolAddress((void**)&p_xn, g_xn);
    cudaGetSymbolAddress((void**)&p_qkv, g_qkv);
    cudaGetSymbolAddress((void**)&p_Pb, g_Pb);
    cudaGetSymbolAddress((void**)&p_Pv, g_Pv);
    cudaGetSymbolAddress((void**)&p_y, g_y);
    cudaGetSymbolAddress((void**)&p_xn2, g_xn2);
    cudaGetSymbolAddress((void**)&p_h1a, g_h1a);
    cudaGetSymbolAddress((void**)&p_h1b, g_h1b);
    cudaGetSymbolAddress((void**)&p_h1, g_h1);

    dim3 gthr(32, 8);

    // 1. LN1
    ln_kernel<<<NB, 256>>>(x, ln1_w, ln1_b, p_xn);
    // 2. QKV = xn @ qkv_w^T + qkv_b    [512,768]
    gemm_xwt<<<dim3((QKVD + 31) / 32, (NB + 31) / 32), gthr>>>(
        p_xn, qkv_w, qkv_b, nullptr, p_qkv, NB, QKVD, DD);
    // 3. coords projections
    proj3_kernel<<<NB, 256>>>(coords, rb1_w, rv1_w, p_Pb, p_Pv);
    // 4. fused attention -> y = x + attn_out
    attn_kernel<<<NB, 256>>>(x, p_qkv, p_Pb, p_Pv, rb1_b, rb2_w, rb2_b,
                             rv1_b, rv2_w, rv2_b, p_y);
    // 5. LN2
    ln_kernel<<<NB, 256>>>(p_y, ln2_w, ln2_b, p_xn2);
    // 6. FFN up projections
    gemm_xwt<<<dim3((HID + 31) / 32, (NB + 31) / 32), gthr>>>(
        p_xn2, ffn_w1, ffn_b1, nullptr, p_h1a, NB, HID, DD);
    gemm_xwt<<<dim3((HID + 31) / 32, (NB + 31) / 32), gthr>>>(
        p_xn2, ffn_w2, ffn_b2, nullptr, p_h1b, NB, HID, DD);
    // 7. SwiGLU combine
    {
        int n = NB * HID;
        ffn_combine<<<(n + 255) / 256, 256>>>(p_h1a, p_h1b, p_h1, n);
    }
    // 8. out = h1 @ ffn_w3^T + ffn_b3 + y
    gemm_xwt<<<dim3((DD + 31) / 32, (NB + 31) / 32), gthr>>>(
        p_h1, ffn_w3, ffn_b3, p_y, out, NB, DD, HID);
}

// round 3
// speedup vs baseline: 2.0248x; 2.0248x over previous
#include <cuda_runtime.h>
#include <cuda_bf16.h>

// Shapes (compile-time constants)
#define NB   512           // sequence length
#define DD   256           // model dim
#define HH   8             // heads
#define HID  682           // swiglu hidden
#define QKVD 768

// ---------------- device scratch ----------------
__device__ float g_xn[NB * DD];
__device__ float g_qkv[NB * QKVD];
__device__ float g_KT[DD * NB];      // K transposed [k][j]
__device__ float g_Pb[NB * DD];
__device__ float g_PbT[DD * NB];     // Pb transposed [k][j]
__device__ float g_Pv[NB * DD];
__device__ float g_rv2T[DD * DD];    // rv2 transposed [k][d]
__device__ float g_y[NB * DD];
__device__ float g_xn2[NB * DD];
__device__ float g_h1[NB * HID];

__device__ __forceinline__ float silu_f(float v) {
    return v * __frcp_rn(1.0f + __expf(-v));
}

// ---------------- LayerNorm: one block per row, 256 threads ----------------
__global__ __launch_bounds__(256) void ln_kernel(const float* __restrict__ x,
                                                 const float* __restrict__ w,
                                                 const float* __restrict__ b,
                                                 float* __restrict__ out) {
    int row = blockIdx.x, t = threadIdx.x;
    float v = x[row * DD + t];
    float s = v, q = v * v;
#pragma unroll
    for (int o = 16; o; o >>= 1) {
        s += __shfl_xor_sync(0xffffffff, s, o);
        q += __shfl_xor_sync(0xffffffff, q, o);
    }
    __shared__ float ss[8], sq[8];
    int warp = t >> 5, lane = t & 31;
    if (lane == 0) { ss[warp] = s; sq[warp] = q; }
    __syncthreads();
    s = 0.f; q = 0.f;
#pragma unroll
    for (int k = 0; k < 8; k++) { s += ss[k]; q += sq[k]; }
    float mean = s * (1.0f / DD);
    float var = q * (1.0f / DD) - mean * mean;
    out[row * DD + t] = (v - mean) * rsqrtf(var + 1e-5f) * w[t] + b[t];
}

// ---------------- coords projection ----------------
__global__ __launch_bounds__(256) void proj3_kernel(const float* __restrict__ coords,
                                                    const float* __restrict__ rb1,
                                                    const float* __restrict__ rv1,
                                                    float* __restrict__ Pb,
                                                    float* __restrict__ PbT,
                                                    float* __restrict__ Pv) {
    int i = blockIdx.x, k = threadIdx.x;
    float c0 = coords[i * 3 + 0], c1 = coords[i * 3 + 1], c2 = coords[i * 3 + 2];
    float pb = rb1[k * 3 + 0] * c0 + rb1[k * 3 + 1] * c1 + rb1[k * 3 + 2] * c2;
    float pv = rv1[k * 3 + 0] * c0 + rv1[k * 3 + 1] * c1 + rv1[k * 3 + 2] * c2;
    Pb[i * DD + k] = pb;
    PbT[k * NB + i] = pb;
    Pv[i * DD + k] = pv;
}

// ---------------- generic 32x32-tiled transpose ----------------
// out[c*R + r] = in[r*ldin + off + c];  R,C multiples of 32
__global__ __launch_bounds__(256) void transpose_kernel(const float* __restrict__ in,
                                                        float* __restrict__ out,
                                                        int R, int C, int ldin, int off) {
    __shared__ float tile[32][33];
    int c0 = blockIdx.x * 32, r0 = blockIdx.y * 32;
    int tx = threadIdx.x, ty = threadIdx.y;  // 32 x 8
#pragma unroll
    for (int s = 0; s < 32; s += 8)
        tile[ty + s][tx] = in[(r0 + ty + s) * ldin + off + c0 + tx];
    __syncthreads();
#pragma unroll
    for (int s = 0; s < 32; s += 8)
        out[(c0 + ty + s) * R + r0 + tx] = tile[tx][ty + s];
}

// ---------------- GEMM: C = A @ W^T (+bias) (+residual), 64x64 tile ----------------
__global__ __launch_bounds__(256, 2) void gemm64(const float* __restrict__ A,
                                                 const float* __restrict__ W,
                                                 const float* __restrict__ bias,
                                                 const float* __restrict__ residual,
                                                 float* __restrict__ C,
                                                 int M, int N, int K) {
    __shared__ float As[64][33];
    __shared__ float Ws[64][33];
    int tid = threadIdx.x;
    int tx = tid & 15, ty = tid >> 4;
    int row0 = blockIdx.y * 64, col0 = blockIdx.x * 64;
    float acc[4][4] = {};
    for (int k0 = 0; k0 < K; k0 += 32) {
#pragma unroll
        for (int l = 0; l < 8; l++) {
            int idx = l * 256 + tid;
            int m = idx >> 5, k = idx & 31;
            int gk = k0 + k;
            int ar = row0 + m, wr = col0 + m;
            As[m][k] = (ar < M && gk < K) ? A[ar * K + gk] : 0.f;
            Ws[m][k] = (wr < N && gk < K) ? W[wr * K + gk] : 0.f;
        }
        __syncthreads();
#pragma unroll
        for (int kk = 0; kk < 32; kk++) {
            float a[4], b[4];
#pragma unroll
            for (int r = 0; r < 4; r++) a[r] = As[ty * 4 + r][kk];
#pragma unroll
            for (int r = 0; r < 4; r++) b[r] = Ws[tx * 4 + r][kk];
#pragma unroll
            for (int r = 0; r < 4; r++)
#pragma unroll
                for (int c = 0; c < 4; c++) acc[r][c] += a[r] * b[c];
        }
        __syncthreads();
    }
#pragma unroll
    for (int r = 0; r < 4; r++) {
        int m = row0 + ty * 4 + r;
        if (m >= M) continue;
#pragma unroll
        for (int c = 0; c < 4; c++) {
            int n = col0 + tx * 4 + c;
            if (n >= N) continue;
            float v = acc[r][c];
            if (bias) v += bias[n];
            if (residual) v += residual[m * N + n];
            C[m * N + n] = v;
        }
    }
}

// ---------------- fused SwiGLU dual-GEMM: H = silu(A@W1^T+b1) * (A@W2^T+b2) ----------
__global__ __launch_bounds__(256, 2) void gemm_swiglu(const float* __restrict__ A,
                                                      const float* __restrict__ W1,
                                                      const float* __restrict__ b1,
                                                      const float* __restrict__ W2,
                                                      const float* __restrict__ b2,
                                                      float* __restrict__ Hout,
                                                      int M, int N, int K) {
    __shared__ float As[64][33];
    __shared__ float W1s[64][33];
    __shared__ float W2s[64][33];
    int tid = threadIdx.x;
    int tx = tid & 15, ty = tid >> 4;
    int row0 = blockIdx.y * 64, col0 = blockIdx.x * 64;
    float acc1[4][4] = {};
    float acc2[4][4] = {};
    for (int k0 = 0; k0 < K; k0 += 32) {
#pragma unroll
        for (int l = 0; l < 8; l++) {
            int idx = l * 256 + tid;
            int m = idx >> 5, k = idx & 31;
            int gk = k0 + k;
            int ar = row0 + m, wr = col0 + m;
            As[m][k] = (ar < M && gk < K) ? A[ar * K + gk] : 0.f;
            W1s[m][k] = (wr < N && gk < K) ? W1[wr * K + gk] : 0.f;
            W2s[m][k] = (wr < N && gk < K) ? W2[wr * K + gk] : 0.f;
        }
        __syncthreads();
#pragma unroll
        for (int kk = 0; kk < 32; kk++) {
            float a[4], b[4], c[4];
#pragma unroll
            for (int r = 0; r < 4; r++) a[r] = As[ty * 4 + r][kk];
#pragma unroll
            for (int r = 0; r < 4; r++) b[r] = W1s[tx * 4 + r][kk];
#pragma unroll
            for (int r = 0; r < 4; r++) c[r] = W2s[tx * 4 + r][kk];
#pragma unroll
            for (int r = 0; r < 4; r++)
#pragma unroll
                for (int cc = 0; cc < 4; cc++) {
                    acc1[r][cc] += a[r] * b[cc];
                    acc2[r][cc] += a[r] * c[cc];
                }
        }
        __syncthreads();
    }
#pragma unroll
    for (int r = 0; r < 4; r++) {
        int m = row0 + ty * 4 + r;
        if (m >= M) continue;
#pragma unroll
        for (int c = 0; c < 4; c++) {
            int n = col0 + tx * 4 + c;
            if (n >= N) continue;
            float v1 = acc1[r][c] + b1[n];
            float v2 = acc2[r][c] + b2[n];
            Hout[m * N + n] = silu_f(v1) * v2;
        }
    }
}

// ---------------- fused attention: one block per query i ----------------
__global__ __launch_bounds__(256, 3) void attn_kernel(
    const float* __restrict__ x, const float* __restrict__ qkv,
    const float* __restrict__ KT, const float* __restrict__ Pb,
    const float* __restrict__ PbT, const float* __restrict__ Pv,
    const float* __restrict__ rb1_b, const float* __restrict__ rb2_w,
    const float* __restrict__ rb2_b, const float* __restrict__ rv1_b,
    const float* __restrict__ rv2T, const float* __restrict__ rv2_b,
    float* __restrict__ y) {
    const int i = blockIdx.x;
    const int t = threadIdx.x;

    __shared__ __align__(16) float2 sm_qpq[DD];      // (q[k], Pbq[k])
    __shared__ __align__(16) float sm_rb2T[DD * HH]; // rb2 transposed [k][h]
    __shared__ __align__(16) float sm_w[NB * HH];    // logits -> weights [j][h]
    __shared__ __align__(16) float sm_T[HH * DD];    // [h][k]

    sm_qpq[t] = make_float2(qkv[i * QKVD + t], Pb[i * DD + t] + rb1_b[t]);
#pragma unroll
    for (int h = 0; h < HH; h++) sm_rb2T[t * HH + h] = rb2_w[h * DD + t];
    __syncthreads();

    const float4* rb2T4 = (const float4*)sm_rb2T;

    // ---- Phase A: logits for j0 = t, j1 = t+256 ----
    // qk must be per-head (32 dims per head) -> h outer loop, k = h*32+kk
    {
        const int j0 = t, j1 = t + 256;
        float b0[HH] = {}, b1[HH] = {};
        float qa0[HH], qa1[HH];
#pragma unroll
        for (int h = 0; h < HH; h++) {
            float qk0 = 0.f, qk1 = 0.f;
#pragma unroll 4
            for (int kk = 0; kk < 32; kk++) {
                int k = h * 32 + kk;
                float kv0 = KT[k * NB + j0];
                float kv1 = KT[k * NB + j1];
                float pb0 = PbT[k * NB + j0];
                float pb1 = PbT[k * NB + j1];
                float2 qpq = sm_qpq[k];
                qk0 += qpq.x * kv0;
                qk1 += qpq.x * kv1;
                float u0 = silu_f(qpq.y - pb0);
                float u1 = silu_f(qpq.y - pb1);
                float4 ra = rb2T4[k * 2], rb = rb2T4[k * 2 + 1];
                b0[0] += ra.x * u0; b0[1] += ra.y * u0; b0[2] += ra.z * u0; b0[3] += ra.w * u0;
                b0[4] += rb.x * u0; b0[5] += rb.y * u0; b0[6] += rb.z * u0; b0[7] += rb.w * u0;
                b1[0] += ra.x * u1; b1[1] += ra.y * u1; b1[2] += ra.z * u1; b1[3] += ra.w * u1;
                b1[4] += rb.x * u1; b1[5] += rb.y * u1; b1[6] += rb.z * u1; b1[7] += rb.w * u1;
            }
            qa0[h] = qk0;
            qa1[h] = qk1;
        }
        const float sc = 0.17677669529663687f;
#pragma unroll
        for (int h = 0; h < HH; h++) {
            float bb = rb2_b[h];
            sm_w[j0 * HH + h] = qa0[h] * sc + b0[h] + bb;
            sm_w[j1 * HH + h] = qa1[h] * sc + b1[h] + bb;
        }
    }
    __syncthreads();

    // ---- softmax: warp h handles head h ----
    {
        int h = t >> 5, lane = t & 31;
        float m = -1e30f;
        for (int j = lane; j < NB; j += 32) m = fmaxf(m, sm_w[j * HH + h]);
#pragma unroll
        for (int o = 16; o; o >>= 1) m = fmaxf(m, __shfl_xor_sync(0xffffffff, m, o));
        float s = 0.f;
        for (int j = lane; j < NB; j += 32) {
            float e = __expf(sm_w[j * HH + h] - m);
            sm_w[j * HH + h] = e;
            s += e;
        }
#pragma unroll
        for (int o = 16; o; o >>= 1) s += __shfl_xor_sync(0xffffffff, s, o);
        float inv = 1.0f / s;
        for (int j = lane; j < NB; j += 32) sm_w[j * HH + h] *= inv;
    }
    __syncthreads();

    // ---- Phase B: T[h,k], thread t owns k = t ----
    {
        float pvq = Pv[i * DD + t] + rv1_b[t];
        float T[HH] = {};
        const float4* w4 = (const float4*)sm_w;
#pragma unroll 4
        for (int j = 0; j < NB; j++) {
            float sv = silu_f(pvq - Pv[j * DD + t]);
            float4 w0 = w4[j * 2], w1 = w4[j * 2 + 1];
            T[0] += w0.x * sv; T[1] += w0.y * sv; T[2] += w0.z * sv; T[3] += w0.w * sv;
            T[4] += w1.x * sv; T[5] += w1.y * sv; T[6] += w1.z * sv; T[7] += w1.w * sv;
        }
#pragma unroll
        for (int h = 0; h < HH; h++) sm_T[h * DD + t] = T[h];
    }
    __syncthreads();

    // ---- output: context1 + context2 + residual ----
    {
        const int d = t;
        const int h = d >> 5;
        float c1 = 0.f;
        const float* V = qkv + 2 * DD + d;
#pragma unroll 8
        for (int j = 0; j < NB; j++)
            c1 += sm_w[j * HH + h] * V[j * QKVD];
        float c2 = rv2_b[d];
        const float* Ts = sm_T + h * DD;
#pragma unroll 8
        for (int k = 0; k < DD; k++)
            c2 += rv2T[k * DD + d] * Ts[k];
        y[i * DD + d] = x[i * DD + d] + c1 + c2;
    }
}

// ---------------- host launcher ----------------
extern "C" void kernel_launch(void* const* d_in, const int* in_sizes, int n_in,
                              void* d_out, int out_size) {
    const float* x      = (const float*)d_in[0];
    const float* coords = (const float*)d_in[1];
    const float* ln1_w  = (const float*)d_in[2];
    const float* ln1_b  = (const float*)d_in[3];
    const float* ln2_w  = (const float*)d_in[4];
    const float* ln2_b  = (const float*)d_in[5];
    const float* qkv_w  = (const float*)d_in[6];
    const float* qkv_b  = (const float*)d_in[7];
    const float* rb1_w  = (const float*)d_in[8];
    const float* rb1_b  = (const float*)d_in[9];
    const float* rb2_w  = (const float*)d_in[10];
    const float* rb2_b  = (const float*)d_in[11];
    const float* rv1_w  = (const float*)d_in[12];
    const float* rv1_b  = (const float*)d_in[13];
    const float* rv2_w  = (const float*)d_in[14];
    const float* rv2_b  = (const float*)d_in[15];
    const float* ffn_w1 = (const float*)d_in[16];
    const float* ffn_b1 = (const float*)d_in[17];
    const float* ffn_w2 = (const float*)d_in[18];
    const float* ffn_b2 = (const float*)d_in[19];
    const float* ffn_w3 = (const float*)d_in[20];
    const float* ffn_b3 = (const float*)d_in[21];
    float* out = (float*)d_out;

    float *p_xn, *p_qkv, *p_KT, *p_Pb, *p_PbT, *p_Pv, *p_rv2T, *p_y, *p_xn2, *p_h1;
    cudaGetSymbolAddress((void**)&p_xn, g_xn);
    cudaGetSymbolAddress((void**)&p_qkv, g_qkv);
    cudaGetSymbolAddress((void**)&p_KT, g_KT);
    cudaGetSymbolAddress((void**)&p_Pb, g_Pb);
    cudaGetSymbolAddress((void**)&p_PbT, g_PbT);
    cudaGetSymbolAddress((void**)&p_Pv, g_Pv);
    cudaGetSymbolAddress((void**)&p_rv2T, g_rv2T);
    cudaGetSymbolAddress((void**)&p_y, g_y);
    cudaGetSymbolAddress((void**)&p_xn2, g_xn2);
    cudaGetSymbolAddress((void**)&p_h1, g_h1);

    dim3 tthr(32, 8);

    // 1. LN1
    ln_kernel<<<NB, 256>>>(x, ln1_w, ln1_b, p_xn);
    // 2. QKV = xn @ qkv_w^T + qkv_b    [512,768]
    gemm64<<<dim3(QKVD / 64, NB / 64), 256>>>(p_xn, qkv_w, qkv_b, nullptr, p_qkv,
                                              NB, QKVD, DD);
    // 3. coords projections (Pb, PbT, Pv)
    proj3_kernel<<<NB, 256>>>(coords, rb1_w, rv1_w, p_Pb, p_PbT, p_Pv);
    // 4. K^T from qkv (cols 256..511), rv2^T
    transpose_kernel<<<dim3(DD / 32, NB / 32), tthr>>>(p_qkv, p_KT, NB, DD, QKVD, DD);
    transpose_kernel<<<dim3(DD / 32, DD / 32), tthr>>>(rv2_w, p_rv2T, DD, DD, DD, 0);
    // 5. fused attention -> y = x + attn_out
    attn_kernel<<<NB, 256>>>(x, p_qkv, p_KT, p_Pb, p_PbT, p_Pv, rb1_b, rb2_w, rb2_b,
                             rv1_b, p_rv2T, rv2_b, p_y);
    // 6. LN2
    ln_kernel<<<NB, 256>>>(p_y, ln2_w, ln2_b, p_xn2);
    // 7. fused SwiGLU dual-GEMM
    gemm_swiglu<<<dim3((HID + 63) / 64, NB / 64), 256>>>(p_xn2, ffn_w1, ffn_b1,
                                                         ffn_w2, ffn_b2, p_h1,
                                                         NB, HID, DD);
    // 8. out = h1 @ ffn_w3^T + ffn_b3 + y
    gemm64<<<dim3(DD / 64, NB / 64), 256>>>(p_h1, ffn_w3, ffn_b3, p_y, out,
                                            NB, DD, HID);
}

// round 4
// speedup vs baseline: 2.7399x; 1.3531x over previous
#include <cuda_runtime.h>
#include <cuda_bf16.h>

// Shapes (compile-time constants)
#define NB   512           // sequence length
#define DD   256           // model dim
#define HH   8             // heads
#define HID  682           // swiglu hidden
#define QKVD 768

typedef unsigned long long u64;

// ---------------- device scratch ----------------
__device__ float g_xn[NB * DD];
__device__ float g_qkv[NB * QKVD];
__device__ float g_KT[DD * NB];      // K transposed [k][j]
__device__ float g_Pb[NB * DD];
__device__ float g_PbT[DD * NB];     // Pb transposed [k][j]
__device__ float g_Pv[NB * DD];
__device__ float g_rv2T[DD * DD];    // rv2 transposed [k][d]
__device__ float g_y[NB * DD];
__device__ float g_xn2[NB * DD];
__device__ float g_h1[NB * HID];

__device__ __forceinline__ float silu_f(float v) {
    return v * __frcp_rn(1.0f + __expf(-v));
}

// ---- packed f32x2 helpers (sm_100+) ----
__device__ __forceinline__ u64 pk2(float lo, float hi) {
    u64 r;
    asm("mov.b64 %0, {%1, %2};" : "=l"(r) : "f"(lo), "f"(hi));
    return r;
}
__device__ __forceinline__ float2 up2(u64 v) {
    float2 f;
    asm("mov.b64 {%0, %1}, %2;" : "=f"(f.x), "=f"(f.y) : "l"(v));
    return f;
}
__device__ __forceinline__ u64 fma2(u64 a, u64 b, u64 c) {
    u64 d;
    asm("fma.rn.f32x2 %0, %1, %2, %3;" : "=l"(d) : "l"(a), "l"(b), "l"(c));
    return d;
}
__device__ __forceinline__ u64 add2(u64 a, u64 b) {
    u64 d;
    asm("add.rn.f32x2 %0, %1, %2;" : "=l"(d) : "l"(a), "l"(b));
    return d;
}

// ---------------- LayerNorm: one block per row, 256 threads ----------------
__global__ __launch_bounds__(256) void ln_kernel(const float* __restrict__ x,
                                                 const float* __restrict__ w,
                                                 const float* __restrict__ b,
                                                 float* __restrict__ out) {
    int row = blockIdx.x, t = threadIdx.x;
    float v = x[row * DD + t];
    float s = v, q = v * v;
#pragma unroll
    for (int o = 16; o; o >>= 1) {
        s += __shfl_xor_sync(0xffffffff, s, o);
        q += __shfl_xor_sync(0xffffffff, q, o);
    }
    __shared__ float ss[8], sq[8];
    int warp = t >> 5, lane = t & 31;
    if (lane == 0) { ss[warp] = s; sq[warp] = q; }
    __syncthreads();
    s = 0.f; q = 0.f;
#pragma unroll
    for (int k = 0; k < 8; k++) { s += ss[k]; q += sq[k]; }
    float mean = s * (1.0f / DD);
    float var = q * (1.0f / DD) - mean * mean;
    out[row * DD + t] = (v - mean) * rsqrtf(var + 1e-5f) * w[t] + b[t];
}

// ---------------- coords projection ----------------
__global__ __launch_bounds__(256) void proj3_kernel(const float* __restrict__ coords,
                                                    const float* __restrict__ rb1,
                                                    const float* __restrict__ rv1,
                                                    float* __restrict__ Pb,
                                                    float* __restrict__ PbT,
                                                    float* __restrict__ Pv) {
    int i = blockIdx.x, k = threadIdx.x;
    float c0 = coords[i * 3 + 0], c1 = coords[i * 3 + 1], c2 = coords[i * 3 + 2];
    float pb = rb1[k * 3 + 0] * c0 + rb1[k * 3 + 1] * c1 + rb1[k * 3 + 2] * c2;
    float pv = rv1[k * 3 + 0] * c0 + rv1[k * 3 + 1] * c1 + rv1[k * 3 + 2] * c2;
    Pb[i * DD + k] = pb;
    PbT[k * NB + i] = pb;
    Pv[i * DD + k] = pv;
}

// ---------------- generic 32x32-tiled transpose ----------------
__global__ __launch_bounds__(256) void transpose_kernel(const float* __restrict__ in,
                                                        float* __restrict__ out,
                                                        int R, int C, int ldin, int off) {
    __shared__ float tile[32][33];
    int c0 = blockIdx.x * 32, r0 = blockIdx.y * 32;
    int tx = threadIdx.x, ty = threadIdx.y;  // 32 x 8
#pragma unroll
    for (int s = 0; s < 32; s += 8)
        tile[ty + s][tx] = in[(r0 + ty + s) * ldin + off + c0 + tx];
    __syncthreads();
#pragma unroll
    for (int s = 0; s < 32; s += 8)
        out[(c0 + ty + s) * R + r0 + tx] = tile[tx][ty + s];
}

// ---------------- GEMM: C = A @ W^T (+bias) (+residual), 64x64 tile ----------------
// smem stored k-major: As[k][m], Ws[k][n] so n-pairs are contiguous for LDS.64
__global__ __launch_bounds__(256, 2) void gemm64(const float* __restrict__ A,
                                                 const float* __restrict__ W,
                                                 const float* __restrict__ bias,
                                                 const float* __restrict__ residual,
                                                 float* __restrict__ C,
                                                 int M, int N, int K) {
    __shared__ __align__(16) float As[32][66];
    __shared__ __align__(16) float Ws[32][66];
    int tid = threadIdx.x;
    int tx = tid & 15, ty = tid >> 4;
    int row0 = blockIdx.y * 64, col0 = blockIdx.x * 64;
    u64 acc[4][2] = {};
    for (int k0 = 0; k0 < K; k0 += 32) {
#pragma unroll
        for (int l = 0; l < 8; l++) {
            int idx = l * 256 + tid;
            int m = idx >> 5, k = idx & 31;
            int gk = k0 + k;
            int ar = row0 + m, wr = col0 + m;
            As[k][m] = (ar < M && gk < K) ? A[ar * K + gk] : 0.f;
            Ws[k][m] = (wr < N && gk < K) ? W[wr * K + gk] : 0.f;
        }
        __syncthreads();
#pragma unroll
        for (int kk = 0; kk < 32; kk++) {
            const u64* bp = (const u64*)&Ws[kk][tx * 4];
            u64 b0 = bp[0], b1 = bp[1];
            float2 a01 = *(const float2*)&As[kk][ty * 4];
            float2 a23 = *(const float2*)&As[kk][ty * 4 + 2];
            u64 aa0 = pk2(a01.x, a01.x), aa1 = pk2(a01.y, a01.y);
            u64 aa2 = pk2(a23.x, a23.x), aa3 = pk2(a23.y, a23.y);
            acc[0][0] = fma2(aa0, b0, acc[0][0]); acc[0][1] = fma2(aa0, b1, acc[0][1]);
            acc[1][0] = fma2(aa1, b0, acc[1][0]); acc[1][1] = fma2(aa1, b1, acc[1][1]);
            acc[2][0] = fma2(aa2, b0, acc[2][0]); acc[2][1] = fma2(aa2, b1, acc[2][1]);
            acc[3][0] = fma2(aa3, b0, acc[3][0]); acc[3][1] = fma2(aa3, b1, acc[3][1]);
        }
        __syncthreads();
    }
#pragma unroll
    for (int r = 0; r < 4; r++) {
        int m = row0 + ty * 4 + r;
        if (m >= M) continue;
#pragma unroll
        for (int c2 = 0; c2 < 2; c2++) {
            float2 v = up2(acc[r][c2]);
            int n0 = col0 + tx * 4 + c2 * 2;
            if (n0 < N) {
                float o = v.x;
                if (bias) o += bias[n0];
                if (residual) o += residual[m * N + n0];
                C[m * N + n0] = o;
            }
            if (n0 + 1 < N) {
                float o = v.y;
                if (bias) o += bias[n0 + 1];
                if (residual) o += residual[m * N + n0 + 1];
                C[m * N + n0 + 1] = o;
            }
        }
    }
}

// ---------------- fused SwiGLU dual-GEMM: H = silu(A@W1^T+b1) * (A@W2^T+b2) ----------
__global__ __launch_bounds__(256, 2) void gemm_swiglu(const float* __restrict__ A,
                                                      const float* __restrict__ W1,
                                                      const float* __restrict__ b1,
                                                      const float* __restrict__ W2,
                                                      const float* __restrict__ b2,
                                                      float* __restrict__ Hout,
                                                      int M, int N, int K) {
    __shared__ __align__(16) float As[32][66];
    __shared__ __align__(16) float W1s[32][66];
    __shared__ __align__(16) float W2s[32][66];
    int tid = threadIdx.x;
    int tx = tid & 15, ty = tid >> 4;
    int row0 = blockIdx.y * 64, col0 = blockIdx.x * 64;
    u64 acc1[4][2] = {};
    u64 acc2[4][2] = {};
    for (int k0 = 0; k0 < K; k0 += 32) {
#pragma unroll
        for (int l = 0; l < 8; l++) {
            int idx = l * 256 + tid;
            int m = idx >> 5, k = idx & 31;
            int gk = k0 + k;
            int ar = row0 + m, wr = col0 + m;
            As[k][m] = (ar < M && gk < K) ? A[ar * K + gk] : 0.f;
            W1s[k][m] = (wr < N && gk < K) ? W1[wr * K + gk] : 0.f;
            W2s[k][m] = (wr < N && gk < K) ? W2[wr * K + gk] : 0.f;
        }
        __syncthreads();
#pragma unroll
        for (int kk = 0; kk < 32; kk++) {
            const u64* b1p = (const u64*)&W1s[kk][tx * 4];
            const u64* b2p = (const u64*)&W2s[kk][tx * 4];
            u64 p0 = b1p[0], p1 = b1p[1];
            u64 q0 = b2p[0], q1 = b2p[1];
            float2 a01 = *(const float2*)&As[kk][ty * 4];
            float2 a23 = *(const float2*)&As[kk][ty * 4 + 2];
            u64 aa0 = pk2(a01.x, a01.x), aa1 = pk2(a01.y, a01.y);
            u64 aa2 = pk2(a23.x, a23.x), aa3 = pk2(a23.y, a23.y);
            acc1[0][0] = fma2(aa0, p0, acc1[0][0]); acc1[0][1] = fma2(aa0, p1, acc1[0][1]);
            acc1[1][0] = fma2(aa1, p0, acc1[1][0]); acc1[1][1] = fma2(aa1, p1, acc1[1][1]);
            acc1[2][0] = fma2(aa2, p0, acc1[2][0]); acc1[2][1] = fma2(aa2, p1, acc1[2][1]);
            acc1[3][0] = fma2(aa3, p0, acc1[3][0]); acc1[3][1] = fma2(aa3, p1, acc1[3][1]);
            acc2[0][0] = fma2(aa0, q0, acc2[0][0]); acc2[0][1] = fma2(aa0, q1, acc2[0][1]);
            acc2[1][0] = fma2(aa1, q0, acc2[1][0]); acc2[1][1] = fma2(aa1, q1, acc2[1][1]);
            acc2[2][0] = fma2(aa2, q0, acc2[2][0]); acc2[2][1] = fma2(aa2, q1, acc2[2][1]);
            acc2[3][0] = fma2(aa3, q0, acc2[3][0]); acc2[3][1] = fma2(aa3, q1, acc2[3][1]);
        }
        __syncthreads();
    }
#pragma unroll
    for (int r = 0; r < 4; r++) {
        int m = row0 + ty * 4 + r;
        if (m >= M) continue;
#pragma unroll
        for (int c2 = 0; c2 < 2; c2++) {
            float2 v1 = up2(acc1[r][c2]);
            float2 v2 = up2(acc2[r][c2]);
            int n0 = col0 + tx * 4 + c2 * 2;
            if (n0 < N)
                Hout[m * N + n0] = silu_f(v1.x + b1[n0]) * (v2.x + b2[n0]);
            if (n0 + 1 < N)
                Hout[m * N + n0 + 1] = silu_f(v1.y + b1[n0 + 1]) * (v2.y + b2[n0 + 1]);
        }
    }
}

// ---------------- fused attention: one block per TWO queries ----------------
__global__ __launch_bounds__(256, 2) void attn_kernel(
    const float* __restrict__ x, const float* __restrict__ qkv,
    const float* __restrict__ KT, const float* __restrict__ Pb,
    const float* __restrict__ PbT, const float* __restrict__ Pv,
    const float* __restrict__ rb1_b, const float* __restrict__ rb2_w,
    const float* __restrict__ rb2_b, const float* __restrict__ rv1_b,
    const float* __restrict__ rv2T, const float* __restrict__ rv2_b,
    float* __restrict__ y) {
    const int i0 = blockIdx.x * 2;
    const int t = threadIdx.x;

    __shared__ __align__(16) float2 sm_qpq[2][DD];     // (q[k], Pbq[k]) per query
    __shared__ __align__(16) float sm_rb2[DD * HH];    // rb2 transposed [k][h]
    __shared__ __align__(16) float sm_w[2][NB * HH];   // logits -> weights [q][j][h]
    __shared__ __align__(16) float sm_T[2][HH * DD];   // [q][h][k]

#pragma unroll
    for (int q = 0; q < 2; q++) {
        int iq = i0 + q;
        sm_qpq[q][t] = make_float2(qkv[iq * QKVD + t], Pb[iq * DD + t] + rb1_b[t]);
    }
#pragma unroll
    for (int h = 0; h < HH; h++) sm_rb2[t * HH + h] = rb2_w[h * DD + t];
    __syncthreads();

    // ---- Phase A: logits for (q in {0,1}) x (j0 = t, j1 = t+256) ----
    {
        const int j0 = t, j1 = t + 256;
        u64 bias[2][2][4] = {};   // [q][jslot][head pair]
        const float sc = 0.17677669529663687f;
#pragma unroll
        for (int h = 0; h < HH; h++) {
            u64 qk[2] = {0ull, 0ull};   // packed over (j0, j1)
#pragma unroll 4
            for (int kk = 0; kk < 32; kk++) {
                int k = h * 32 + kk;
                float kv0 = KT[k * NB + j0];
                float kv1 = KT[k * NB + j1];
                float pb0 = PbT[k * NB + j0];
                float pb1 = PbT[k * NB + j1];
                u64 kvp = pk2(kv0, kv1);
                const u64* r2 = (const u64*)(sm_rb2 + k * HH);
                u64 r20 = r2[0], r21 = r2[1], r22 = r2[2], r23 = r2[3];
#pragma unroll
                for (int q = 0; q < 2; q++) {
                    float2 qp = sm_qpq[q][k];
                    qk[q] = fma2(pk2(qp.x, qp.x), kvp, qk[q]);
                    float u0 = silu_f(qp.y - pb0);
                    float u1 = silu_f(qp.y - pb1);
                    u64 u0p = pk2(u0, u0);
                    u64 u1p = pk2(u1, u1);
                    bias[q][0][0] = fma2(u0p, r20, bias[q][0][0]);
                    bias[q][0][1] = fma2(u0p, r21, bias[q][0][1]);
                    bias[q][0][2] = fma2(u0p, r22, bias[q][0][2]);
                    bias[q][0][3] = fma2(u0p, r23, bias[q][0][3]);
                    bias[q][1][0] = fma2(u1p, r20, bias[q][1][0]);
                    bias[q][1][1] = fma2(u1p, r21, bias[q][1][1]);
                    bias[q][1][2] = fma2(u1p, r22, bias[q][1][2]);
                    bias[q][1][3] = fma2(u1p, r23, bias[q][1][3]);
                }
            }
            // fold qk*sc into bias pair c = h>>1, slot h&1
            int c = h >> 1;
#pragma unroll
            for (int q = 0; q < 2; q++) {
                float2 qv = up2(qk[q]);
                float s0 = qv.x * sc, s1 = qv.y * sc;
                u64 p0 = (h & 1) ? pk2(0.f, s0) : pk2(s0, 0.f);
                u64 p1 = (h & 1) ? pk2(0.f, s1) : pk2(s1, 0.f);
                bias[q][0][c] = add2(bias[q][0][c], p0);
                bias[q][1][c] = add2(bias[q][1][c], p1);
            }
        }
#pragma unroll
        for (int c = 0; c < 4; c++) {
            u64 bb = pk2(rb2_b[2 * c], rb2_b[2 * c + 1]);
            *(u64*)(&sm_w[0][j0 * HH + 2 * c]) = add2(bias[0][0][c], bb);
            *(u64*)(&sm_w[0][j1 * HH + 2 * c]) = add2(bias[0][1][c], bb);
            *(u64*)(&sm_w[1][j0 * HH + 2 * c]) = add2(bias[1][0][c], bb);
            *(u64*)(&sm_w[1][j1 * HH + 2 * c]) = add2(bias[1][1][c], bb);
        }
    }
    __syncthreads();

    // ---- softmax: warp h handles head h, loop over both queries ----
    {
        int h = t >> 5, lane = t & 31;
#pragma unroll
        for (int q = 0; q < 2; q++) {
            float* wq = sm_w[q];
            float m = -1e30f;
            for (int j = lane; j < NB; j += 32) m = fmaxf(m, wq[j * HH + h]);
#pragma unroll
            for (int o = 16; o; o >>= 1) m = fmaxf(m, __shfl_xor_sync(0xffffffff, m, o));
            float s = 0.f;
            for (int j = lane; j < NB; j += 32) {
                float e = __expf(wq[j * HH + h] - m);
                wq[j * HH + h] = e;
                s += e;
            }
#pragma unroll
            for (int o = 16; o; o >>= 1) s += __shfl_xor_sync(0xffffffff, s, o);
            float inv = 1.0f / s;
            for (int j = lane; j < NB; j += 32) wq[j * HH + h] *= inv;
        }
    }
    __syncthreads();

    // ---- Phase B: T[q][h,k], thread t owns k = t ----
    {
        float pvb = rv1_b[t];
        float pvq0 = Pv[i0 * DD + t] + pvb;
        float pvq1 = Pv[(i0 + 1) * DD + t] + pvb;
        u64 T0[4] = {}, T1[4] = {};
#pragma unroll 2
        for (int j = 0; j < NB; j++) {
            float pv = Pv[j * DD + t];
            float s0 = silu_f(pvq0 - pv);
            float s1 = silu_f(pvq1 - pv);
            u64 s0p = pk2(s0, s0), s1p = pk2(s1, s1);
            const u64* w0 = (const u64*)(sm_w[0] + j * HH);
            const u64* w1 = (const u64*)(sm_w[1] + j * HH);
            T0[0] = fma2(s0p, w0[0], T0[0]); T0[1] = fma2(s0p, w0[1], T0[1]);
            T0[2] = fma2(s0p, w0[2], T0[2]); T0[3] = fma2(s0p, w0[3], T0[3]);
            T1[0] = fma2(s1p, w1[0], T1[0]); T1[1] = fma2(s1p, w1[1], T1[1]);
            T1[2] = fma2(s1p, w1[2], T1[2]); T1[3] = fma2(s1p, w1[3], T1[3]);
        }
#pragma unroll
        for (int c = 0; c < 4; c++) {
            float2 a = up2(T0[c]);
            sm_T[0][(2 * c) * DD + t] = a.x;
            sm_T[0][(2 * c + 1) * DD + t] = a.y;
            float2 b = up2(T1[c]);
            sm_T[1][(2 * c) * DD + t] = b.x;
            sm_T[1][(2 * c + 1) * DD + t] = b.y;
        }
    }
    __syncthreads();

    // ---- output: context1 + context2 + residual, for both queries ----
    {
        const int d = t;
        const int h = d >> 5;
        float c1a = 0.f, c1b = 0.f;
        const float* V = qkv + 2 * DD;
#pragma unroll 8
        for (int j = 0; j < NB; j++) {
            float v = V[j * QKVD + d];
            c1a += sm_w[0][j * HH + h] * v;
            c1b += sm_w[1][j * HH + h] * v;
        }
        float bv = rv2_b[d];
        float c2a = bv, c2b = bv;
        const float* T0s = sm_T[0] + h * DD;
        const float* T1s = sm_T[1] + h * DD;
#pragma unroll 8
        for (int k = 0; k < DD; k++) {
            float rv = rv2T[k * DD + d];
            c2a += rv * T0s[k];
            c2b += rv * T1s[k];
        }
        y[i0 * DD + d] = x[i0 * DD + d] + c1a + c2a;
        y[(i0 + 1) * DD + d] = x[(i0 + 1) * DD + d] + c1b + c2b;
    }
}

// ---------------- host launcher ----------------
extern "C" void kernel_launch(void* const* d_in, const int* in_sizes, int n_in,
                              void* d_out, int out_size) {
    const float* x      = (const float*)d_in[0];
    const float* coords = (const float*)d_in[1];
    const float* ln1_w  = (const float*)d_in[2];
    const float* ln1_b  = (const float*)d_in[3];
    const float* ln2_w  = (const float*)d_in[4];
    const float* ln2_b  = (const float*)d_in[5];
    const float* qkv_w  = (const float*)d_in[6];
    const float* qkv_b  = (const float*)d_in[7];
    const float* rb1_w  = (const float*)d_in[8];
    const float* rb1_b  = (const float*)d_in[9];
    const float* rb2_w  = (const float*)d_in[10];
    const float* rb2_b  = (const float*)d_in[11];
    const float* rv1_w  = (const float*)d_in[12];
    const float* rv1_b  = (const float*)d_in[13];
    const float* rv2_w  = (const float*)d_in[14];
    const float* rv2_b  = (const float*)d_in[15];
    const float* ffn_w1 = (const float*)d_in[16];
    const float* ffn_b1 = (const float*)d_in[17];
    const float* ffn_w2 = (const float*)d_in[18];
    const float* ffn_b2 = (const float*)d_in[19];
    const float* ffn_w3 = (const float*)d_in[20];
    const float* ffn_b3 = (const float*)d_in[21];
    float* out = (float*)d_out;

    float *p_xn, *p_qkv, *p_KT, *p_Pb, *p_PbT, *p_Pv, *p_rv2T, *p_y, *p_xn2, *p_h1;
    cudaGetSymbolAddress((void**)&p_xn, g_xn);
    cudaGetSymbolAddress((void**)&p_qkv, g_qkv);
    cudaGetSymbolAddress((void**)&p_KT, g_KT);
    cudaGetSymbolAddress((void**)&p_Pb, g_Pb);
    cudaGetSymbolAddress((void**)&p_PbT, g_PbT);
    cudaGetSymbolAddress((void**)&p_Pv, g_Pv);
    cudaGetSymbolAddress((void**)&p_rv2T, g_rv2T);
    cudaGetSymbolAddress((void**)&p_y, g_y);
    cudaGetSymbolAddress((void**)&p_xn2, g_xn2);
    cudaGetSymbolAddress((void**)&p_h1, g_h1);

    dim3 tthr(32, 8);

    // 1. LN1
    ln_kernel<<<NB, 256>>>(x, ln1_w, ln1_b, p_xn);
    // 2. QKV = xn @ qkv_w^T + qkv_b    [512,768]
    gemm64<<<dim3(QKVD / 64, NB / 64), 256>>>(p_xn, qkv_w, qkv_b, nullptr, p_qkv,
                                              NB, QKVD, DD);
    // 3. coords projections (Pb, PbT, Pv)
    proj3_kernel<<<NB, 256>>>(coords, rb1_w, rv1_w, p_Pb, p_PbT, p_Pv);
    // 4. K^T from qkv (cols 256..511), rv2^T
    transpose_kernel<<<dim3(DD / 32, NB / 32), tthr>>>(p_qkv, p_KT, NB, DD, QKVD, DD);
    transpose_kernel<<<dim3(DD / 32, DD / 32), tthr>>>(rv2_w, p_rv2T, DD, DD, DD, 0);
    // 5. fused attention (2 queries per block) -> y = x + attn_out
    attn_kernel<<<NB / 2, 256>>>(x, p_qkv, p_KT, p_Pb, p_PbT, p_Pv, rb1_b, rb2_w,
                                 rb2_b, rv1_b, p_rv2T, rv2_b, p_y);
    // 6. LN2
    ln_kernel<<<NB, 256>>>(p_y, ln2_w, ln2_b, p_xn2);
    // 7. fused SwiGLU dual-GEMM
    gemm_swiglu<<<dim3((HID + 63) / 64, NB / 64), 256>>>(p_xn2, ffn_w1, ffn_b1,
                                                         ffn_w2, ffn_b2, p_h1,
                                                         NB, HID, DD);
    // 8. out = h1 @ ffn_w3^T + ffn_b3 + y
    gemm64<<<dim3(DD / 64, NB / 64), 256>>>(p_h1, ffn_w3, ffn_b3, p_y, out,
                                            NB, DD, HID);
}

// round 5
// speedup vs baseline: 4.3742x; 1.5965x over previous
#include <cuda_runtime.h>
#include <cuda_bf16.h>

// Shapes (compile-time constants)
#define NB   512           // sequence length
#define DD   256           // model dim
#define HH   8             // heads
#define HID  682           // swiglu hidden
#define QKVD 768

typedef unsigned long long u64;

// ---------------- device scratch ----------------
__device__ float g_xn[NB * DD];
__device__ float g_qkv[NB * QKVD];
__device__ float g_KT[DD * NB];      // K transposed [k][j]
__device__ float g_Pb[NB * DD];
__device__ float g_PbT[DD * NB];     // Pb transposed [k][j]
__device__ float g_Pv[NB * DD];
__device__ float g_rv2T[DD * DD];    // rv2 transposed [k][d]
__device__ float g_w[NB * NB * HH];  // softmax weights [i][j*HH+h]  (8MB)
__device__ float g_y[NB * DD];
__device__ float g_xn2[NB * DD];
__device__ float g_h1[NB * HID];

// ---- packed f32x2 helpers (sm_100+) ----
__device__ __forceinline__ u64 pk2(float lo, float hi) {
    u64 r;
    asm("mov.b64 %0, {%1, %2};" : "=l"(r) : "f"(lo), "f"(hi));
    return r;
}
__device__ __forceinline__ float2 up2(u64 v) {
    float2 f;
    asm("mov.b64 {%0, %1}, %2;" : "=f"(f.x), "=f"(f.y) : "l"(v));
    return f;
}
__device__ __forceinline__ u64 fma2(u64 a, u64 b, u64 c) {
    u64 d;
    asm("fma.rn.f32x2 %0, %1, %2, %3;" : "=l"(d) : "l"(a), "l"(b), "l"(c));
    return d;
}
__device__ __forceinline__ u64 add2(u64 a, u64 b) {
    u64 d;
    asm("add.rn.f32x2 %0, %1, %2;" : "=l"(d) : "l"(a), "l"(b));
    return d;
}

// fast silu: v * rcp.approx(1 + exp(-v))  (rel err ~1e-7)
__device__ __forceinline__ float silu_f(float v) {
    float e = __expf(-v);
    float r;
    asm("rcp.approx.f32 %0, %1;" : "=f"(r) : "f"(1.0f + e));
    return v * r;
}
// accurate silu for the (cold) FFN epilogue
__device__ __forceinline__ float silu_acc(float v) {
    return v / (1.0f + __expf(-v));
}

// ---------------- LayerNorm: one block per row, 256 threads ----------------
__global__ __launch_bounds__(256) void ln_kernel(const float* __restrict__ x,
                                                 const float* __restrict__ w,
                                                 const float* __restrict__ b,
                                                 float* __restrict__ out) {
    int row = blockIdx.x, t = threadIdx.x;
    float v = x[row * DD + t];
    float s = v, q = v * v;
#pragma unroll
    for (int o = 16; o; o >>= 1) {
        s += __shfl_xor_sync(0xffffffff, s, o);
        q += __shfl_xor_sync(0xffffffff, q, o);
    }
    __shared__ float ss[8], sq[8];
    int warp = t >> 5, lane = t & 31;
    if (lane == 0) { ss[warp] = s; sq[warp] = q; }
    __syncthreads();
    s = 0.f; q = 0.f;
#pragma unroll
    for (int k = 0; k < 8; k++) { s += ss[k]; q += sq[k]; }
    float mean = s * (1.0f / DD);
    float var = q * (1.0f / DD) - mean * mean;
    out[row * DD + t] = (v - mean) * rsqrtf(var + 1e-5f) * w[t] + b[t];
}

// ---------------- coords projection ----------------
__global__ __launch_bounds__(256) void proj3_kernel(const float* __restrict__ coords,
                                                    const float* __restrict__ rb1,
                                                    const float* __restrict__ rv1,
                                                    float* __restrict__ Pb,
                                                    float* __restrict__ PbT,
                                                    float* __restrict__ Pv) {
    int i = blockIdx.x, k = threadIdx.x;
    float c0 = coords[i * 3 + 0], c1 = coords[i * 3 + 1], c2 = coords[i * 3 + 2];
    float pb = rb1[k * 3 + 0] * c0 + rb1[k * 3 + 1] * c1 + rb1[k * 3 + 2] * c2;
    float pv = rv1[k * 3 + 0] * c0 + rv1[k * 3 + 1] * c1 + rv1[k * 3 + 2] * c2;
    Pb[i * DD + k] = pb;
    PbT[k * NB + i] = pb;
    Pv[i * DD + k] = pv;
}

// ---------------- generic 32x32-tiled transpose ----------------
__global__ __launch_bounds__(256) void transpose_kernel(const float* __restrict__ in,
                                                        float* __restrict__ out,
                                                        int R, int C, int ldin, int off) {
    __shared__ float tile[32][33];
    int c0 = blockIdx.x * 32, r0 = blockIdx.y * 32;
    int tx = threadIdx.x, ty = threadIdx.y;  // 32 x 8
#pragma unroll
    for (int s = 0; s < 32; s += 8)
        tile[ty + s][tx] = in[(r0 + ty + s) * ldin + off + c0 + tx];
    __syncthreads();
#pragma unroll
    for (int s = 0; s < 32; s += 8)
        out[(c0 + ty + s) * R + r0 + tx] = tile[tx][ty + s];
}

// ---------------- GEMM: C = A @ W^T (+bias)(+residual), 32x64 tile ----------------
// As holds duplicated pairs (a,a) as u64 -> inner loop = 2x LDS.128 + 4 FFMA2
__global__ __launch_bounds__(256, 2) void gemm_t(const float* __restrict__ A,
                                                 const float* __restrict__ W,
                                                 const float* __restrict__ bias,
                                                 const float* __restrict__ residual,
                                                 float* __restrict__ C,
                                                 int M, int N, int K) {
    __shared__ __align__(16) u64 As[32][34];     // [k][m] duplicated
    __shared__ __align__(16) float Ws[32][68];   // [k][n]
    int tid = threadIdx.x;
    int tx = tid & 15, ty = tid >> 4;            // tx -> n (4 cols), ty -> m (2 rows)
    int row0 = blockIdx.y * 32, col0 = blockIdx.x * 64;
    u64 acc[2][2] = {};
    for (int k0 = 0; k0 < K; k0 += 32) {
#pragma unroll
        for (int l = 0; l < 4; l++) {            // A: 32x32
            int idx = l * 256 + tid;
            int m = idx >> 5, k = idx & 31;
            int gk = k0 + k, ar = row0 + m;
            float v = (ar < M && gk < K) ? A[ar * K + gk] : 0.f;
            As[k][m] = pk2(v, v);
        }
#pragma unroll
        for (int l = 0; l < 8; l++) {            // W: 64x32
            int idx = l * 256 + tid;
            int m = idx >> 5, k = idx & 31;
            int gk = k0 + k, wr = col0 + m;
            Ws[k][m] = (wr < N && gk < K) ? W[wr * K + gk] : 0.f;
        }
        __syncthreads();
#pragma unroll
        for (int kk = 0; kk < 32; kk++) {
            ulonglong2 Av = *(const ulonglong2*)&As[kk][ty * 2];
            ulonglong2 Bv = *(const ulonglong2*)&Ws[kk][tx * 4];
            acc[0][0] = fma2(Av.x, Bv.x, acc[0][0]);
            acc[0][1] = fma2(Av.x, Bv.y, acc[0][1]);
            acc[1][0] = fma2(Av.y, Bv.x, acc[1][0]);
            acc[1][1] = fma2(Av.y, Bv.y, acc[1][1]);
        }
        __syncthreads();
    }
#pragma unroll
    for (int r = 0; r < 2; r++) {
        int m = row0 + ty * 2 + r;
        if (m >= M) continue;
#pragma unroll
        for (int c2 = 0; c2 < 2; c2++) {
            float2 v = up2(acc[r][c2]);
            int n0 = col0 + tx * 4 + c2 * 2;
            if (n0 < N) {
                float o = v.x;
                if (bias) o += bias[n0];
                if (residual) o += residual[m * N + n0];
                C[m * N + n0] = o;
            }
            if (n0 + 1 < N) {
                float o = v.y;
                if (bias) o += bias[n0 + 1];
                if (residual) o += residual[m * N + n0 + 1];
                C[m * N + n0 + 1] = o;
            }
        }
    }
}

// ---------------- fused SwiGLU dual-GEMM, 32x64 tile ----------------
__global__ __launch_bounds__(256, 2) void gemm_swiglu(const float* __restrict__ A,
                                                      const float* __restrict__ W1,
                                                      const float* __restrict__ b1,
                                                      const float* __restrict__ W2,
                                                      const float* __restrict__ b2,
                                                      float* __restrict__ Hout,
                                                      int M, int N, int K) {
    __shared__ __align__(16) u64 As[32][34];
    __shared__ __align__(16) float W1s[32][68];
    __shared__ __align__(16) float W2s[32][68];
    int tid = threadIdx.x;
    int tx = tid & 15, ty = tid >> 4;
    int row0 = blockIdx.y * 32, col0 = blockIdx.x * 64;
    u64 acc1[2][2] = {};
    u64 acc2[2][2] = {};
    for (int k0 = 0; k0 < K; k0 += 32) {
#pragma unroll
        for (int l = 0; l < 4; l++) {
            int idx = l * 256 + tid;
            int m = idx >> 5, k = idx & 31;
            int gk = k0 + k, ar = row0 + m;
            float v = (ar < M && gk < K) ? A[ar * K + gk] : 0.f;
            As[k][m] = pk2(v, v);
        }
#pragma unroll
        for (int l = 0; l < 8; l++) {
            int idx = l * 256 + tid;
            int m = idx >> 5, k = idx & 31;
            int gk = k0 + k, wr = col0 + m;
            W1s[k][m] = (wr < N && gk < K) ? W1[wr * K + gk] : 0.f;
            W2s[k][m] = (wr < N && gk < K) ? W2[wr * K + gk] : 0.f;
        }
        __syncthreads();
#pragma unroll
        for (int kk = 0; kk < 32; kk++) {
            ulonglong2 Av = *(const ulonglong2*)&As[kk][ty * 2];
            ulonglong2 Bv = *(const ulonglong2*)&W1s[kk][tx * 4];
            ulonglong2 Cv = *(const ulonglong2*)&W2s[kk][tx * 4];
            acc1[0][0] = fma2(Av.x, Bv.x, acc1[0][0]);
            acc1[0][1] = fma2(Av.x, Bv.y, acc1[0][1]);
            acc1[1][0] = fma2(Av.y, Bv.x, acc1[1][0]);
            acc1[1][1] = fma2(Av.y, Bv.y, acc1[1][1]);
            acc2[0][0] = fma2(Av.x, Cv.x, acc2[0][0]);
            acc2[0][1] = fma2(Av.x, Cv.y, acc2[0][1]);
            acc2[1][0] = fma2(Av.y, Cv.x, acc2[1][0]);
            acc2[1][1] = fma2(Av.y, Cv.y, acc2[1][1]);
        }
        __syncthreads();
    }
#pragma unroll
    for (int r = 0; r < 2; r++) {
        int m = row0 + ty * 2 + r;
        if (m >= M) continue;
#pragma unroll
        for (int c2 = 0; c2 < 2; c2++) {
            float2 v1 = up2(acc1[r][c2]);
            float2 v2 = up2(acc2[r][c2]);
            int n0 = col0 + tx * 4 + c2 * 2;
            if (n0 < N)
                Hout[m * N + n0] = silu_acc(v1.x + b1[n0]) * (v2.x + b2[n0]);
            if (n0 + 1 < N)
                Hout[m * N + n0 + 1] = silu_acc(v1.y + b1[n0 + 1]) * (v2.y + b2[n0 + 1]);
        }
    }
}

// ---------------- attention part 1: logits + softmax -> g_w ----------------
__global__ __launch_bounds__(256, 3) void attn_logits(
    const float* __restrict__ qkv, const float* __restrict__ KT,
    const float* __restrict__ Pb, const float* __restrict__ PbT,
    const float* __restrict__ rb1_b, const float* __restrict__ rb2_w,
    const float* __restrict__ rb2_b, float* __restrict__ gw_all) {
    const int i0 = blockIdx.x * 2;
    const int t = threadIdx.x;

    __shared__ __align__(16) float2 sm_qpq[2][DD];     // (q[k], Pbq[k]) per query
    __shared__ __align__(16) float sm_rb2[DD * HH];    // rb2 transposed [k][h]
    __shared__ __align__(16) float sm_w[2][NB * HH];   // logits -> weights [q][j][h]

#pragma unroll
    for (int q = 0; q < 2; q++) {
        int iq = i0 + q;
        sm_qpq[q][t] = make_float2(qkv[iq * QKVD + t], Pb[iq * DD + t] + rb1_b[t]);
    }
#pragma unroll
    for (int h = 0; h < HH; h++) sm_rb2[t * HH + h] = rb2_w[h * DD + t];
    __syncthreads();

    // ---- Phase A: logits for (q in {0,1}) x (j0 = t, j1 = t+256) ----
    {
        const int j0 = t, j1 = t + 256;
        u64 bias[2][2][4] = {};   // [q][jslot][head pair]
        const float sc = 0.17677669529663687f;
#pragma unroll
        for (int h = 0; h < HH; h++) {
            u64 qk[2] = {0ull, 0ull};   // packed over (j0, j1)
#pragma unroll 4
            for (int kk = 0; kk < 32; kk++) {
                int k = h * 32 + kk;
                float kv0 = KT[k * NB + j0];
                float kv1 = KT[k * NB + j1];
                float pb0 = PbT[k * NB + j0];
                float pb1 = PbT[k * NB + j1];
                u64 kvp = pk2(kv0, kv1);
                ulonglong2 rA = *(const ulonglong2*)(sm_rb2 + k * HH);
                ulonglong2 rB = *(const ulonglong2*)(sm_rb2 + k * HH + 4);
#pragma unroll
                for (int q = 0; q < 2; q++) {
                    float2 qp = sm_qpq[q][k];
                    qk[q] = fma2(pk2(qp.x, qp.x), kvp, qk[q]);
                    float u0 = silu_f(qp.y - pb0);
                    float u1 = silu_f(qp.y - pb1);
                    u64 u0p = pk2(u0, u0);
                    u64 u1p = pk2(u1, u1);
                    bias[q][0][0] = fma2(u0p, rA.x, bias[q][0][0]);
                    bias[q][0][1] = fma2(u0p, rA.y, bias[q][0][1]);
                    bias[q][0][2] = fma2(u0p, rB.x, bias[q][0][2]);
                    bias[q][0][3] = fma2(u0p, rB.y, bias[q][0][3]);
                    bias[q][1][0] = fma2(u1p, rA.x, bias[q][1][0]);
                    bias[q][1][1] = fma2(u1p, rA.y, bias[q][1][1]);
                    bias[q][1][2] = fma2(u1p, rB.x, bias[q][1][2]);
                    bias[q][1][3] = fma2(u1p, rB.y, bias[q][1][3]);
                }
            }
            // fold qk*sc into bias pair c = h>>1, slot h&1
            int c = h >> 1;
#pragma unroll
            for (int q = 0; q < 2; q++) {
                float2 qv = up2(qk[q]);
                float s0 = qv.x * sc, s1 = qv.y * sc;
                u64 p0 = (h & 1) ? pk2(0.f, s0) : pk2(s0, 0.f);
                u64 p1 = (h & 1) ? pk2(0.f, s1) : pk2(s1, 0.f);
                bias[q][0][c] = add2(bias[q][0][c], p0);
                bias[q][1][c] = add2(bias[q][1][c], p1);
            }
        }
#pragma unroll
        for (int c = 0; c < 4; c++) {
            u64 bb = pk2(rb2_b[2 * c], rb2_b[2 * c + 1]);
            *(u64*)(&sm_w[0][j0 * HH + 2 * c]) = add2(bias[0][0][c], bb);
            *(u64*)(&sm_w[0][j1 * HH + 2 * c]) = add2(bias[0][1][c], bb);
            *(u64*)(&sm_w[1][j0 * HH + 2 * c]) = add2(bias[1][0][c], bb);
            *(u64*)(&sm_w[1][j1 * HH + 2 * c]) = add2(bias[1][1][c], bb);
        }
    }
    __syncthreads();

    // ---- softmax: warp h handles head h, loop over both queries ----
    {
        int h = t >> 5, lane = t & 31;
#pragma unroll
        for (int q = 0; q < 2; q++) {
            float* wq = sm_w[q];
            float m = -1e30f;
            for (int j = lane; j < NB; j += 32) m = fmaxf(m, wq[j * HH + h]);
#pragma unroll
            for (int o = 16; o; o >>= 1) m = fmaxf(m, __shfl_xor_sync(0xffffffff, m, o));
            float s = 0.f;
            for (int j = lane; j < NB; j += 32) {
                float e = __expf(wq[j * HH + h] - m);
                wq[j * HH + h] = e;
                s += e;
            }
#pragma unroll
            for (int o = 16; o; o >>= 1) s += __shfl_xor_sync(0xffffffff, s, o);
            float inv = 1.0f / s;
            for (int j = lane; j < NB; j += 32) wq[j * HH + h] *= inv;
        }
    }
    __syncthreads();

    // ---- bulk copy weights to gmem ----
    {
        float4* dst = (float4*)(gw_all + i0 * NB * HH);
        const float4* src = (const float4*)sm_w;
#pragma unroll
        for (int idx = t; idx < 2 * NB * HH / 4; idx += 256) dst[idx] = src[idx];
    }
}

// ---------------- attention part 2: T accumulation + context + output ---------------
__global__ __launch_bounds__(256, 3) void attn_out(
    const float* __restrict__ x, const float* __restrict__ qkv,
    const float* __restrict__ Pv, const float* __restrict__ rv1_b,
    const float* __restrict__ rv2T, const float* __restrict__ rv2_b,
    const float* __restrict__ gw_all, float* __restrict__ y) {
    const int i0 = blockIdx.x * 2;
    const int t = threadIdx.x;

    __shared__ __align__(16) float sm_T[2][HH * DD];   // [q][h][k], 16KB

    const float* gw0 = gw_all + i0 * NB * HH;
    const float* gw1 = gw0 + NB * HH;

    // ---- Phase B: T[q][h,k], thread t owns k = t ----
    {
        float pvb = rv1_b[t];
        float pvq0 = Pv[i0 * DD + t] + pvb;
        float pvq1 = Pv[(i0 + 1) * DD + t] + pvb;
        u64 T0[4] = {}, T1[4] = {};
#pragma unroll 2
        for (int j = 0; j < NB; j++) {
            float pv = Pv[j * DD + t];
            float s0 = silu_f(pvq0 - pv);
            float s1 = silu_f(pvq1 - pv);
            u64 s0p = pk2(s0, s0), s1p = pk2(s1, s1);
            ulonglong2 wA0 = *(const ulonglong2*)(gw0 + j * HH);
            ulonglong2 wA1 = *(const ulonglong2*)(gw0 + j * HH + 4);
            ulonglong2 wB0 = *(const ulonglong2*)(gw1 + j * HH);
            ulonglong2 wB1 = *(const ulonglong2*)(gw1 + j * HH + 4);
            T0[0] = fma2(s0p, wA0.x, T0[0]); T0[1] = fma2(s0p, wA0.y, T0[1]);
            T0[2] = fma2(s0p, wA1.x, T0[2]); T0[3] = fma2(s0p, wA1.y, T0[3]);
            T1[0] = fma2(s1p, wB0.x, T1[0]); T1[1] = fma2(s1p, wB0.y, T1[1]);
            T1[2] = fma2(s1p, wB1.x, T1[2]); T1[3] = fma2(s1p, wB1.y, T1[3]);
        }
#pragma unroll
        for (int c = 0; c < 4; c++) {
            float2 a = up2(T0[c]);
            sm_T[0][(2 * c) * DD + t] = a.x;
            sm_T[0][(2 * c + 1) * DD + t] = a.y;
            float2 b = up2(T1[c]);
            sm_T[1][(2 * c) * DD + t] = b.x;
            sm_T[1][(2 * c + 1) * DD + t] = b.y;
        }
    }
    __syncthreads();

    // ---- output: context1 + context2 + residual, for both queries ----
    {
        const int d = t;
        const int h = d >> 5;
        float c1a = 0.f, c1b = 0.f;
        const float* V = qkv + 2 * DD;
#pragma unroll 8
        for (int j = 0; j < NB; j++) {
            float v = V[j * QKVD + d];
            c1a += gw0[j * HH + h] * v;
            c1b += gw1[j * HH + h] * v;
        }
        float bv = rv2_b[d];
        float c2a = bv, c2b = bv;
        const float* T0s = sm_T[0] + h * DD;
        const float* T1s = sm_T[1] + h * DD;
#pragma unroll 8
        for (int k = 0; k < DD; k++) {
            float rv = rv2T[k * DD + d];
            c2a += rv * T0s[k];
            c2b += rv * T1s[k];
        }
        y[i0 * DD + d] = x[i0 * DD + d] + c1a + c2a;
        y[(i0 + 1) * DD + d] = x[(i0 + 1) * DD + d] + c1b + c2b;
    }
}

// ---------------- host launcher ----------------
extern "C" void kernel_launch(void* const* d_in, const int* in_sizes, int n_in,
                              void* d_out, int out_size) {
    const float* x      = (const float*)d_in[0];
    const float* coords = (const float*)d_in[1];
    const float* ln1_w  = (const float*)d_in[2];
    const float* ln1_b  = (const float*)d_in[3];
    const float* ln2_w  = (const float*)d_in[4];
    const float* ln2_b  = (const float*)d_in[5];
    const float* qkv_w  = (const float*)d_in[6];
    const float* qkv_b  = (const float*)d_in[7];
    const float* rb1_w  = (const float*)d_in[8];
    const float* rb1_b  = (const float*)d_in[9];
    const float* rb2_w  = (const float*)d_in[10];
    const float* rb2_b  = (const float*)d_in[11];
    const float* rv1_w  = (const float*)d_in[12];
    const float* rv1_b  = (const float*)d_in[13];
    const float* rv2_w  = (const float*)d_in[14];
    const float* rv2_b  = (const float*)d_in[15];
    const float* ffn_w1 = (const float*)d_in[16];
    const float* ffn_b1 = (const float*)d_in[17];
    const float* ffn_w2 = (const float*)d_in[18];
    const float* ffn_b2 = (const float*)d_in[19];
    const float* ffn_w3 = (const float*)d_in[20];
    const float* ffn_b3 = (const float*)d_in[21];
    float* out = (float*)d_out;

    float *p_xn, *p_qkv, *p_KT, *p_Pb, *p_PbT, *p_Pv, *p_rv2T, *p_w, *p_y, *p_xn2, *p_h1;
    cudaGetSymbolAddress((void**)&p_xn, g_xn);
    cudaGetSymbolAddress((void**)&p_qkv, g_qkv);
    cudaGetSymbolAddress((void**)&p_KT, g_KT);
    cudaGetSymbolAddress((void**)&p_Pb, g_Pb);
    cudaGetSymbolAddress((void**)&p_PbT, g_PbT);
    cudaGetSymbolAddress((void**)&p_Pv, g_Pv);
    cudaGetSymbolAddress((void**)&p_rv2T, g_rv2T);
    cudaGetSymbolAddress((void**)&p_w, g_w);
    cudaGetSymbolAddress((void**)&p_y, g_y);
    cudaGetSymbolAddress((void**)&p_xn2, g_xn2);
    cudaGetSymbolAddress((void**)&p_h1, g_h1);

    dim3 tthr(32, 8);

    // 1. LN1
    ln_kernel<<<NB, 256>>>(x, ln1_w, ln1_b, p_xn);
    // 2. QKV = xn @ qkv_w^T + qkv_b    [512,768]
    gemm_t<<<dim3(QKVD / 64, NB / 32), 256>>>(p_xn, qkv_w, qkv_b, nullptr, p_qkv,
                                              NB, QKVD, DD);
    // 3. coords projections (Pb, PbT, Pv)
    proj3_kernel<<<NB, 256>>>(coords, rb1_w, rv1_w, p_Pb, p_PbT, p_Pv);
    // 4. K^T from qkv (cols 256..511), rv2^T
    transpose_kernel<<<dim3(DD / 32, NB / 32), tthr>>>(p_qkv, p_KT, NB, DD, QKVD, DD);
    transpose_kernel<<<dim3(DD / 32, DD / 32), tthr>>>(rv2_w, p_rv2T, DD, DD, DD, 0);
    // 5. attention part 1: logits + softmax
    attn_logits<<<NB / 2, 256>>>(p_qkv, p_KT, p_Pb, p_PbT, rb1_b, rb2_w, rb2_b, p_w);
    // 6. attention part 2: T + context + output (y = x + attn_out)
    attn_out<<<NB / 2, 256>>>(x, p_qkv, p_Pv, rv1_b, p_rv2T, rv2_b, p_w, p_y);
    // 7. LN2
    ln_kernel<<<NB, 256>>>(p_y, ln2_w, ln2_b, p_xn2);
    // 8. fused SwiGLU dual-GEMM
    gemm_swiglu<<<dim3((HID + 63) / 64, NB / 32), 256>>>(p_xn2, ffn_w1, ffn_b1,
                                                         ffn_w2, ffn_b2, p_h1,
                                                         NB, HID, DD);
    // 9. out = h1 @ ffn_w3^T + ffn_b3 + y
    gemm_t<<<dim3(DD / 64, NB / 32), 256>>>(p_h1, ffn_w3, ffn_b3, p_y, out,
                                            NB, DD, HID);
}